// round 1
// baseline (speedup 1.0000x reference)
#include <cuda_runtime.h>
#include <math.h>

#define D     256      // feature dim (fixed by problem)
#define NT    256      // threads per block
#define NWARP (NT/32)
#define CAP   8192     // gate cache rows per chunk (32 KB shared)

// Load segment id index i, supporting both int64 and int32 storage.
__device__ __forceinline__ long long load_seg(const void* seg, int i, bool is64) {
    if (is64) return ((const long long*)seg)[i];
    return (long long)((const int*)seg)[i];
}

__global__ __launch_bounds__(NT) void gap_kernel(
    const float* __restrict__ feat,     // [N, D]
    const float* __restrict__ Wg,       // [D, 1]
    const float* __restrict__ bg,       // [1]
    const void*  __restrict__ seg,      // [N] sorted, int64 or int32
    int N,
    float* __restrict__ out)            // [B, D]
{
    __shared__ float sW[D];
    __shared__ float sE[CAP];
    __shared__ float sRed[NWARP];
    __shared__ float sBcast[2];

    const int b    = blockIdx.x;
    const int tid  = threadIdx.x;
    const int warp = tid >> 5;
    const int lane = tid & 31;

    sW[tid] = Wg[tid];
    const float bias = bg[0];

    // ---- dtype sniff: if ids are int64 (values < 2^31), the high word of the
    // last 8 bytes is 0; if int32, that word is the last sorted id (~B-1 != 0).
    const bool is64 = (((const int*)seg)[N - 1] == 0);

    // ---- binary search for [start, end) of segment b (all threads redundantly;
    //      loads broadcast within the warp, L1-resident across the block)
    const long long tb = (long long)b;
    int lo = 0, hi = N;
    while (lo < hi) { int mid = (lo + hi) >> 1; if (load_seg(seg, mid, is64) <  tb) lo = mid + 1; else hi = mid; }
    const int start = lo;
    hi = N;
    while (lo < hi) { int mid = (lo + hi) >> 1; if (load_seg(seg, mid, is64) <= tb) lo = mid + 1; else hi = mid; }
    const int end = lo;
    const int cnt = end - start;

    if (cnt == 0) {                      // empty segment: segment_sum identity = 0
        out[(size_t)b * D + tid] = 0.0f;
        return;
    }
    __syncthreads();                     // sW visible

    float m    = -INFINITY;              // running max (uniform across block)
    float ssum = 0.0f;                   // running exp-sum
    float acc  = 0.0f;                   // thread-owned column accumulator

    for (int base = 0; base < cnt; base += CAP) {
        const int cn = min(CAP, cnt - base);

        // ---- pass 1: gates (warp per row), cache raw gate in sE, track max
        float wmax = -INFINITY;
        for (int r = warp; r < cn; r += NWARP) {
            const float4* row = (const float4*)(feat + (size_t)(start + base + r) * D);
            const float4* w4  = (const float4*)sW;
            float4 a0 = row[lane];      float4 w0 = w4[lane];
            float4 a1 = row[lane + 32]; float4 w1 = w4[lane + 32];
            float s = a0.x*w0.x + a0.y*w0.y + a0.z*w0.z + a0.w*w0.w
                    + a1.x*w1.x + a1.y*w1.y + a1.z*w1.z + a1.w*w1.w;
            #pragma unroll
            for (int o = 16; o > 0; o >>= 1) s += __shfl_xor_sync(0xffffffffu, s, o);
            s += bias;
            if (lane == 0) sE[r] = s;
            wmax = fmaxf(wmax, s);       // s uniform across lanes after xor-reduce
        }
        if (lane == 0) sRed[warp] = wmax;
        __syncthreads();                 // also publishes sE
        if (tid == 0) {
            float mm = sRed[0];
            #pragma unroll
            for (int i = 1; i < NWARP; i++) mm = fmaxf(mm, sRed[i]);
            sBcast[0] = mm;
        }
        __syncthreads();
        const float cm = sBcast[0];
        const float nm = fmaxf(m, cm);
        const float scale = (m == -INFINITY) ? 0.0f : __expf(m - nm);
        ssum *= scale;
        acc  *= scale;

        // ---- pass 2: exponentiate in place, block-reduce chunk sum
        float ls = 0.0f;
        for (int r = tid; r < cn; r += NT) {
            float e = __expf(sE[r] - nm);
            sE[r] = e;
            ls += e;
        }
        #pragma unroll
        for (int o = 16; o > 0; o >>= 1) ls += __shfl_xor_sync(0xffffffffu, ls, o);
        if (lane == 0) sRed[warp] = ls;
        __syncthreads();                 // also publishes exp'd sE
        if (tid == 0) {
            float t = 0.0f;
            #pragma unroll
            for (int i = 0; i < NWARP; i++) t += sRed[i];
            sBcast[1] = t;
        }
        __syncthreads();
        ssum += sBcast[1];

        // ---- pass 3: weighted accumulate (thread per column; L2-resident rows)
        const float* fp = feat + (size_t)(start + base) * D + tid;
        int r = 0;
        for (; r + 4 <= cn; r += 4) {
            float e0 = sE[r], e1 = sE[r+1], e2 = sE[r+2], e3 = sE[r+3];
            float f0 = fp[(size_t)(r  ) * D];
            float f1 = fp[(size_t)(r+1) * D];
            float f2 = fp[(size_t)(r+2) * D];
            float f3 = fp[(size_t)(r+3) * D];
            acc += e0 * f0; acc += e1 * f1; acc += e2 * f2; acc += e3 * f3;
        }
        for (; r < cn; r++) acc += sE[r] * fp[(size_t)r * D];

        m = nm;
        __syncthreads();                 // protect sE before next chunk
    }

    out[(size_t)b * D + tid] = acc / ssum;
}

extern "C" void kernel_launch(void* const* d_in, const int* in_sizes, int n_in,
                              void* d_out, int out_size) {
    const float* feat = (const float*)d_in[0];
    const float* Wg   = (const float*)d_in[1];
    const float* bg   = (const float*)d_in[2];
    const void*  seg  = d_in[3];
    const int N = in_sizes[0] / D;
    const int B = out_size / D;
    gap_kernel<<<B, NT>>>(feat, Wg, bg, seg, N, (float*)d_out);
}

// round 2
// speedup vs baseline: 1.9415x; 1.9415x over previous
#include <cuda_runtime.h>
#include <math.h>

#define D     256      // feature dim (fixed)
#define NT    256      // threads per block
#define NWARP (NT/32)

// Load segment id at index i, supporting int64 or int32 storage.
__device__ __forceinline__ long long load_seg(const void* seg, int i, bool is64) {
    if (is64) return ((const long long*)seg)[i];
    return (long long)((const int*)seg)[i];
}

__global__ __launch_bounds__(NT) void gap_kernel(
    const float* __restrict__ feat,     // [N, D]
    const float* __restrict__ Wg,       // [D]
    const float* __restrict__ bg,       // [1]
    const void*  __restrict__ seg,      // [N] sorted
    int N,
    float* __restrict__ out)            // [B, D]
{
    __shared__ float sW[D];
    __shared__ float sAcc[NWARP][D];    // 8 KB: per-warp distributed accumulators
    __shared__ float sM[NWARP];
    __shared__ float sS[NWARP];
    __shared__ float sTot[2];           // [0]=global max M, [1]=total exp-sum

    const int b    = blockIdx.x;
    const int tid  = threadIdx.x;
    const int warp = tid >> 5;
    const int lane = tid & 31;

    sW[tid] = Wg[tid];
    const float bias = bg[0];

    // dtype sniff: int64 ids (< 2^31) have zero high word at the tail; int32 doesn't.
    const bool is64 = (((const int*)seg)[N - 1] == 0);

    // binary search for [start, end) of segment b (redundant per thread; L1-resident)
    const long long tb = (long long)b;
    int lo = 0, hi = N;
    while (lo < hi) { int mid = (lo + hi) >> 1; if (load_seg(seg, mid, is64) <  tb) lo = mid + 1; else hi = mid; }
    const int start = lo;
    hi = N;
    while (lo < hi) { int mid = (lo + hi) >> 1; if (load_seg(seg, mid, is64) <= tb) lo = mid + 1; else hi = mid; }
    const int cnt = lo - start;

    if (cnt == 0) {                      // empty segment -> zeros (segment_sum identity)
        out[(size_t)b * D + tid] = 0.0f;
        return;
    }
    __syncthreads();                     // sW visible

    // weight registers (row layout matches feat loads)
    const float4 w0 = ((const float4*)sW)[lane];
    const float4 w1 = ((const float4*)sW)[lane + 32];

    // per-warp online-softmax state + distributed register accumulator
    float m    = -INFINITY;
    float ssum = 0.0f;
    float acc[8];
    #pragma unroll
    for (int j = 0; j < 8; j++) acc[j] = 0.0f;

    const float* fbase = feat + (size_t)start * D;

    // macro-free row processor
    auto process = [&](float4 a0, float4 a1) {
        float s = a0.x*w0.x + a0.y*w0.y + a0.z*w0.z + a0.w*w0.w
                + a1.x*w1.x + a1.y*w1.y + a1.z*w1.z + a1.w*w1.w;
        #pragma unroll
        for (int o = 16; o > 0; o >>= 1) s += __shfl_xor_sync(0xffffffffu, s, o);
        s += bias;                       // lane-uniform
        if (s > m) {                     // divergence-free: s uniform across warp
            const float sc = __expf(m - s);   // exp(-inf)=0 handles first row
            ssum *= sc;
            #pragma unroll
            for (int j = 0; j < 8; j++) acc[j] *= sc;
            m = s;
        }
        const float e = __expf(s - m);
        ssum += e;
        acc[0] += e * a0.x; acc[1] += e * a0.y; acc[2] += e * a0.z; acc[3] += e * a0.w;
        acc[4] += e * a1.x; acc[5] += e * a1.y; acc[6] += e * a1.z; acc[7] += e * a1.w;
    };

    // 2-row unrolled main loop: batch 4 outstanding LDG.128 per warp for MLP
    int r = warp;
    for (; r + NWARP < cnt; r += 2 * NWARP) {
        const float4* row0 = (const float4*)(fbase + (size_t)r * D);
        const float4* row1 = (const float4*)(fbase + (size_t)(r + NWARP) * D);
        float4 a0 = row0[lane];
        float4 a1 = row0[lane + 32];
        float4 c0 = row1[lane];
        float4 c1 = row1[lane + 32];
        process(a0, a1);
        process(c0, c1);
    }
    for (; r < cnt; r += NWARP) {
        const float4* row = (const float4*)(fbase + (size_t)r * D);
        process(row[lane], row[lane + 32]);
    }

    // merge the NWARP partial softmax-accumulators
    if (lane == 0) { sM[warp] = m; sS[warp] = ssum; }
    __syncthreads();
    if (tid == 0) {
        float M = sM[0];
        #pragma unroll
        for (int w = 1; w < NWARP; w++) M = fmaxf(M, sM[w]);
        float tot = 0.0f;
        #pragma unroll
        for (int w = 0; w < NWARP; w++) tot += sS[w] * __expf(sM[w] - M);
        sTot[0] = M;
        sTot[1] = tot;
    }
    __syncthreads();
    const float M     = sTot[0];
    const float scale = __expf(m - M);   // m=-inf (warp saw 0 rows) -> 0

    // write scaled accumulator to shared in row layout (float4 stores, conflict-free)
    ((float4*)sAcc[warp])[lane]      = make_float4(acc[0]*scale, acc[1]*scale, acc[2]*scale, acc[3]*scale);
    ((float4*)sAcc[warp])[lane + 32] = make_float4(acc[4]*scale, acc[5]*scale, acc[6]*scale, acc[7]*scale);
    __syncthreads();

    float v = 0.0f;
    #pragma unroll
    for (int w = 0; w < NWARP; w++) v += sAcc[w][tid];
    out[(size_t)b * D + tid] = v / sTot[1];
}

extern "C" void kernel_launch(void* const* d_in, const int* in_sizes, int n_in,
                              void* d_out, int out_size) {
    const float* feat = (const float*)d_in[0];
    const float* Wg   = (const float*)d_in[1];
    const float* bg   = (const float*)d_in[2];
    const void*  seg  = d_in[3];
    const int N = in_sizes[0] / D;
    const int B = out_size / D;
    gap_kernel<<<B, NT>>>(feat, Wg, bg, seg, N, (float*)d_out);
}